// round 1
// baseline (speedup 1.0000x reference)
#include <cuda_runtime.h>
#include <math_constants.h>

// MAM dense: C[n,j] = max_k(x[n,k]*w[j,k]) + min_k(x[n,k]*w[j,k]) + bias[j]
// x: [2048, 512] f32, w: [256, 512] f32, bias: [256] f32, out: [2048, 256] f32
//
// Compute-bound on scalar FP pipes (FMUL + 2x FMNMX per element-k).
// Strategy: 64x64 output tile per CTA, 256 threads, 4x4 register tile,
// K-chunk = 32 staged through padded shared memory (conflict-free),
// gmem->reg prefetch to overlap loads with compute.

constexpr int IN_F  = 512;
constexpr int OUT_F = 256;
constexpr int NROWS = 2048;

constexpr int BN = 64;   // n-tile per block
constexpr int BJ = 64;   // j-tile per block
constexpr int KB = 32;   // k-chunk
constexpr int THREADS = 256;

__global__ __launch_bounds__(THREADS, 1)
void mam_dense_kernel(const float* __restrict__ x,
                      const float* __restrict__ w,
                      const float* __restrict__ bias,
                      float* __restrict__ out)
{
    // +1 pad -> bank-conflict-free for both the strided STS scatter and the
    // per-k LDS reads (bank = (row + k) % 32 spreads across rows).
    __shared__ float xs[BN][KB + 1];
    __shared__ float ws[BJ][KB + 1];

    const int tid = threadIdx.x;
    const int tj  = tid & 15;   // 0..15 -> j groups of 4
    const int tn  = tid >> 4;   // 0..15 -> n groups of 4
    const int n0  = blockIdx.y * BN;
    const int j0  = blockIdx.x * BJ;

    float maxv[4][4], minv[4][4];
#pragma unroll
    for (int i = 0; i < 4; i++)
#pragma unroll
        for (int jj = 0; jj < 4; jj++) {
            maxv[i][jj] = -CUDART_INF_F;
            minv[i][jj] =  CUDART_INF_F;
        }

    // Loader mapping: tile is 64 rows x 32 k = 2048 floats = 512 float4.
    // float4 index f in [0,512): row = f>>3, kq = f&7 (k = kq*4..kq*4+3).
    // Each thread owns f = tid and f = tid + 256 (2 float4 per tile, per tensor).
    const int rA = tid >> 3,         kqA = tid & 7;
    const int rB = (tid + 256) >> 3, kqB = (tid + 256) & 7;

    // Prefetch chunk 0 into registers.
    float4 xrA, xrB, wrA, wrB;
    xrA = *reinterpret_cast<const float4*>(&x[(n0 + rA) * IN_F + kqA * 4]);
    xrB = *reinterpret_cast<const float4*>(&x[(n0 + rB) * IN_F + kqB * 4]);
    wrA = *reinterpret_cast<const float4*>(&w[(j0 + rA) * IN_F + kqA * 4]);
    wrB = *reinterpret_cast<const float4*>(&w[(j0 + rB) * IN_F + kqB * 4]);

    for (int k0 = 0; k0 < IN_F; k0 += KB) {
        // Scatter prefetched registers into padded smem (transpose-free layout:
        // smem row = tensor row, inner = k).
        xs[rA][kqA * 4 + 0] = xrA.x; xs[rA][kqA * 4 + 1] = xrA.y;
        xs[rA][kqA * 4 + 2] = xrA.z; xs[rA][kqA * 4 + 3] = xrA.w;
        xs[rB][kqB * 4 + 0] = xrB.x; xs[rB][kqB * 4 + 1] = xrB.y;
        xs[rB][kqB * 4 + 2] = xrB.z; xs[rB][kqB * 4 + 3] = xrB.w;
        ws[rA][kqA * 4 + 0] = wrA.x; ws[rA][kqA * 4 + 1] = wrA.y;
        ws[rA][kqA * 4 + 2] = wrA.z; ws[rA][kqA * 4 + 3] = wrA.w;
        ws[rB][kqB * 4 + 0] = wrB.x; ws[rB][kqB * 4 + 1] = wrB.y;
        ws[rB][kqB * 4 + 2] = wrB.z; ws[rB][kqB * 4 + 3] = wrB.w;
        __syncthreads();

        // Prefetch next chunk while computing this one.
        const int kn = k0 + KB;
        if (kn < IN_F) {
            xrA = *reinterpret_cast<const float4*>(&x[(n0 + rA) * IN_F + kn + kqA * 4]);
            xrB = *reinterpret_cast<const float4*>(&x[(n0 + rB) * IN_F + kn + kqB * 4]);
            wrA = *reinterpret_cast<const float4*>(&w[(j0 + rA) * IN_F + kn + kqA * 4]);
            wrB = *reinterpret_cast<const float4*>(&w[(j0 + rB) * IN_F + kn + kqB * 4]);
        }

#pragma unroll
        for (int k = 0; k < KB; k++) {
            float a[4], b[4];
#pragma unroll
            for (int i = 0; i < 4; i++)  a[i]  = xs[tn * 4 + i][k];
#pragma unroll
            for (int jj = 0; jj < 4; jj++) b[jj] = ws[tj * 4 + jj][k];
#pragma unroll
            for (int i = 0; i < 4; i++)
#pragma unroll
                for (int jj = 0; jj < 4; jj++) {
                    const float p = a[i] * b[jj];
                    maxv[i][jj] = fmaxf(maxv[i][jj], p);
                    minv[i][jj] = fminf(minv[i][jj], p);
                }
        }
        __syncthreads();
    }

    // Epilogue: C = max + min + bias
#pragma unroll
    for (int i = 0; i < 4; i++) {
        const int n = n0 + tn * 4 + i;
#pragma unroll
        for (int jj = 0; jj < 4; jj++) {
            const int j = j0 + tj * 4 + jj;
            out[n * OUT_F + j] = maxv[i][jj] + minv[i][jj] + bias[j];
        }
    }
}

extern "C" void kernel_launch(void* const* d_in, const int* in_sizes, int n_in,
                              void* d_out, int out_size)
{
    const float* x    = (const float*)d_in[0];   // [2048, 512]
    const float* w    = (const float*)d_in[1];   // [256, 512]
    const float* bias = (const float*)d_in[2];   // [256]
    float* out        = (float*)d_out;           // [2048, 256]

    dim3 grid(OUT_F / BJ, NROWS / BN);  // (4, 32) = 128 CTAs
    mam_dense_kernel<<<grid, THREADS>>>(x, w, bias, out);
}